// round 5
// baseline (speedup 1.0000x reference)
#include <cuda_runtime.h>
#include <math.h>

#define BB 8
#define TT 256
#define DD 12
#define HH 4
#define HD 3
#define NTOK (BB*TT)

// scratch (no cudaMalloc allowed)
__device__ float g_q[NTOK * DD];          // [n][d] token-major, PRE-SCALED by 1/sqrt(3)
__device__ float g_kT[BB * HH * HD * TT]; // [b][h][i][t] key-major rows (float4-aligned)
__device__ float g_vT[BB * HH * HD * TT];

// ---------------------------------------------------------------------------
// K1: QKV projection, smem-staged. 16 tokens/block x 12 dims = 192 threads.
// q written pre-scaled by 1/sqrt(hd).
// ---------------------------------------------------------------------------
__global__ __launch_bounds__(192)
void qkv_kernel(const float* __restrict__ x,
                const float* __restrict__ wq, const float* __restrict__ wk,
                const float* __restrict__ wv,
                const float* __restrict__ bq, const float* __restrict__ bk,
                const float* __restrict__ bv)
{
    const int tid = threadIdx.x;
    const int n0  = blockIdx.x * 16;

    __shared__ float xs[16][DD + 1];
    __shared__ float wqs[DD * DD], wks[DD * DD], wvs[DD * DD];
    __shared__ float bs[3 * DD];

    if (tid < DD * DD) { wqs[tid] = wq[tid]; wks[tid] = wk[tid]; wvs[tid] = wv[tid]; }
    if (tid < DD) { bs[tid] = bq[tid]; bs[DD + tid] = bk[tid]; bs[2 * DD + tid] = bv[tid]; }
    {   // coalesced: 192 floats = 16 rows x 12
        const int r = tid / DD, c = tid - r * DD;
        xs[r][c] = x[n0 * DD + tid];
    }
    __syncthreads();

    const int t = tid / DD;
    const int d = tid - t * DD;
    const int n = n0 + t;

    float aq = bs[d], ak = bs[DD + d], av = bs[2 * DD + d];
    #pragma unroll
    for (int j = 0; j < DD; j++) {
        const float xj = xs[t][j];
        aq += xj * wqs[d * DD + j];
        ak += xj * wks[d * DD + j];
        av += xj * wvs[d * DD + j];
    }
    g_q[n * DD + d] = aq * 0.57735026919f;      // coalesced, pre-scaled

    const int b = n >> 8, tt = n & 255;
    const int h = d / HD, i = d - h * HD;
    const int base = ((b * HH + h) * HD + i) * TT + tt;
    g_kT[base] = ak;
    g_vT[base] = av;
}

// ---------------------------------------------------------------------------
// K2: fused attention + output projection + analytic quantum expvals.
// Block = one token (128 thr). Warp h: head h, 8 keys/lane, no-max softmax
// (scores bounded ~O(10), fp32 safe), cheap split reduction. Warp 0 tail:
// phi = ctx@wo.T + (bo+theta); c = cos(phi); shfl-scan prefix products.
//   out[k] = prod_{j=0..k} c_j (k>=1) ; out[0] = prod_{j=1..11} c_j
// ---------------------------------------------------------------------------
__global__ __launch_bounds__(128)
void attn_quantum_kernel(const float* __restrict__ wo,
                         const float* __restrict__ bo,
                         const float* __restrict__ theta,
                         float* __restrict__ out)
{
    const int tid  = threadIdx.x;
    const int n    = blockIdx.x;
    const int h    = tid >> 5;
    const int lane = tid & 31;
    const int b    = n >> 8;

    __shared__ float ctxs[DD];
    __shared__ float wos[DD * DD];
    __shared__ float bts[DD];

    // cooperative preload (covered by the single __syncthreads below)
    if (tid < DD * DD - 128) wos[128 + tid] = wo[128 + tid];
    wos[tid] = wo[tid];
    if (tid < DD) bts[tid] = bo[tid] + theta[tid];

    // ---- attention: warp h handles head h of token n ----
    const float* qp = g_q + n * DD + h * HD;        // broadcast within warp
    const float q0 = qp[0], q1 = qp[1], q2 = qp[2]; // pre-scaled

    const float4* kb4 = (const float4*)(g_kT + (b * HH + h) * HD * TT);
    const float4* vb4 = (const float4*)(g_vT + (b * HH + h) * HD * TT);
    const float4 kxa = kb4[lane],       kxb = kb4[32 + lane];
    const float4 kya = kb4[64 + lane],  kyb = kb4[96 + lane];
    const float4 kza = kb4[128 + lane], kzb = kb4[160 + lane];
    const float4 vxa = vb4[lane],       vxb = vb4[32 + lane];
    const float4 vya = vb4[64 + lane],  vyb = vb4[96 + lane];
    const float4 vza = vb4[128 + lane], vzb = vb4[160 + lane];

    // exp(score) directly — no max pass (shift-invariant, range-safe)
    float p[8];
    p[0] = __expf(q0*kxa.x + q1*kya.x + q2*kza.x);
    p[1] = __expf(q0*kxa.y + q1*kya.y + q2*kza.y);
    p[2] = __expf(q0*kxa.z + q1*kya.z + q2*kza.z);
    p[3] = __expf(q0*kxa.w + q1*kya.w + q2*kza.w);
    p[4] = __expf(q0*kxb.x + q1*kyb.x + q2*kzb.x);
    p[5] = __expf(q0*kxb.y + q1*kyb.y + q2*kzb.y);
    p[6] = __expf(q0*kxb.z + q1*kyb.z + q2*kzb.z);
    p[7] = __expf(q0*kxb.w + q1*kyb.w + q2*kzb.w);

    float l  = ((p[0]+p[1]) + (p[2]+p[3])) + ((p[4]+p[5]) + (p[6]+p[7]));
    float a0 = p[0]*vxa.x + p[1]*vxa.y + p[2]*vxa.z + p[3]*vxa.w
             + p[4]*vxb.x + p[5]*vxb.y + p[6]*vxb.z + p[7]*vxb.w;
    float a1 = p[0]*vya.x + p[1]*vya.y + p[2]*vya.z + p[3]*vya.w
             + p[4]*vyb.x + p[5]*vyb.y + p[6]*vyb.z + p[7]*vyb.w;
    float a2 = p[0]*vza.x + p[1]*vza.y + p[2]*vza.z + p[3]*vza.w
             + p[4]*vzb.x + p[5]*vzb.y + p[6]*vzb.z + p[7]*vzb.w;

    // split reduction: 2 butterfly levels on all 4, select by lane group,
    // 3 butterfly levels on one value.
    #pragma unroll
    for (int off = 16; off >= 8; off >>= 1) {
        l  += __shfl_xor_sync(0xFFFFFFFFu, l,  off);
        a0 += __shfl_xor_sync(0xFFFFFFFFu, a0, off);
        a1 += __shfl_xor_sync(0xFFFFFFFFu, a1, off);
        a2 += __shfl_xor_sync(0xFFFFFFFFu, a2, off);
    }
    float v = (lane < 8) ? l : (lane < 16) ? a0 : (lane < 24) ? a1 : a2;
    #pragma unroll
    for (int off = 4; off >= 1; off >>= 1)
        v += __shfl_xor_sync(0xFFFFFFFFu, v, off);
    // lanes 0-7: total l ; 8-15: a0 ; 16-23: a1 ; 24-31: a2
    const float ltot = __shfl_sync(0xFFFFFFFFu, v, 0);
    if ((lane & 7) == 0 && lane != 0)
        ctxs[h * HD + (lane >> 3) - 1] = __fdividef(v, ltot);

    __syncthreads();

    // ---- tail: warp 0 only ----
    if (tid < 32) {
        const int w = lane;
        float c = 1.0f;
        if (w < DD) {
            float a = bts[w];
            #pragma unroll
            for (int j = 0; j < DD; j++) a = fmaf(ctxs[j], wos[w * DD + j], a);
            c = __cosf(a);
        }
        // inclusive product scan of d (d_0 = 1, d_w = c_w for 1<=w<12):
        // S_w = c_1 * ... * c_w
        float d = (w >= 1 && w < DD) ? c : 1.0f;
        #pragma unroll
        for (int off = 1; off <= 8; off <<= 1) {
            const float t = __shfl_up_sync(0xFFFFFFFFu, d, off);
            if (lane >= off) d *= t;
        }
        const float c0  = __shfl_sync(0xFFFFFFFFu, c, 0);
        const float s11 = __shfl_sync(0xFFFFFFFFu, d, 11);
        if (w < DD)
            out[n * DD + w] = (w == 0) ? s11 : c0 * d;
    }
}

extern "C" void kernel_launch(void* const* d_in, const int* in_sizes, int n_in,
                              void* d_out, int out_size)
{
    const float* x     = (const float*)d_in[0];
    const float* wq    = (const float*)d_in[1];
    const float* wk    = (const float*)d_in[2];
    const float* wv    = (const float*)d_in[3];
    const float* bq    = (const float*)d_in[4];
    const float* bk    = (const float*)d_in[5];
    const float* bv    = (const float*)d_in[6];
    const float* wo    = (const float*)d_in[7];
    const float* bo    = (const float*)d_in[8];
    const float* theta = (const float*)d_in[9];
    float* out = (float*)d_out;

    qkv_kernel<<<NTOK / 16, 192>>>(x, wq, wk, wv, bq, bk, bv);
    attn_quantum_kernel<<<NTOK, 128>>>(wo, bo, theta, out);
}

// round 6
// speedup vs baseline: 1.1938x; 1.1938x over previous
#include <cuda_runtime.h>
#include <math.h>

#define BB 8
#define TT 256
#define DD 12
#define HH 4
#define HD 3
#define NTOK (BB*TT)

// scratch (no cudaMalloc allowed)
__device__ float g_q[NTOK * DD];          // [n][d] token-major, PRE-SCALED by 1/sqrt(3)
__device__ float g_kT[BB * HH * HD * TT]; // [b][h][i][t] key-major rows (float4-aligned)
__device__ float g_vT[BB * HH * HD * TT];

// ---------------------------------------------------------------------------
// K1: QKV projection, smem-staged. 16 tokens/block x 12 dims = 192 threads.
// q written pre-scaled by 1/sqrt(hd).
// ---------------------------------------------------------------------------
__global__ __launch_bounds__(192)
void qkv_kernel(const float* __restrict__ x,
                const float* __restrict__ wq, const float* __restrict__ wk,
                const float* __restrict__ wv,
                const float* __restrict__ bq, const float* __restrict__ bk,
                const float* __restrict__ bv)
{
    const int tid = threadIdx.x;
    const int n0  = blockIdx.x * 16;

    __shared__ float xs[16][DD + 1];
    __shared__ float wqs[DD * DD], wks[DD * DD], wvs[DD * DD];
    __shared__ float bs[3 * DD];

    if (tid < DD * DD) { wqs[tid] = wq[tid]; wks[tid] = wk[tid]; wvs[tid] = wv[tid]; }
    if (tid < DD) { bs[tid] = bq[tid]; bs[DD + tid] = bk[tid]; bs[2 * DD + tid] = bv[tid]; }
    {   // coalesced: 192 floats = 16 rows x 12
        const int r = tid / DD, c = tid - r * DD;
        xs[r][c] = x[n0 * DD + tid];
    }
    __syncthreads();

    const int t = tid / DD;
    const int d = tid - t * DD;
    const int n = n0 + t;

    float aq = bs[d], ak = bs[DD + d], av = bs[2 * DD + d];
    #pragma unroll
    for (int j = 0; j < DD; j++) {
        const float xj = xs[t][j];
        aq += xj * wqs[d * DD + j];
        ak += xj * wks[d * DD + j];
        av += xj * wvs[d * DD + j];
    }
    g_q[n * DD + d] = aq * 0.57735026919f;      // coalesced, pre-scaled

    const int b = n >> 8, tt = n & 255;
    const int h = d / HD, i = d - h * HD;
    const int base = ((b * HH + h) * HD + i) * TT + tt;
    g_kT[base] = ak;
    g_vT[base] = av;
}

// ---------------------------------------------------------------------------
// K2: fused attention + projection + analytic quantum expvals.
// Block = 4 consecutive tokens; warp h = head h for ALL 4 tokens, K/V held in
// registers across the 4 queries (4x load reuse, cross-token ILP hides shfl
// latency). No-max softmax (scores O(10), fp32-safe). After one barrier,
// warp t runs token t's tail: phi = ctx@wo.T + (bo+theta), c = cos(phi),
//   out[k] = prod_{j=0..k} c_j (k>=1) ; out[0] = prod_{j=1..11} c_j
// ---------------------------------------------------------------------------
__global__ __launch_bounds__(128)
void attn_quantum_kernel(const float* __restrict__ wo,
                         const float* __restrict__ bo,
                         const float* __restrict__ theta,
                         float* __restrict__ out)
{
    const int tid  = threadIdx.x;
    const int h    = tid >> 5;          // warp = head
    const int lane = tid & 31;
    const int n0   = blockIdx.x * 4;    // 4 tokens, same batch (4 | 256)
    const int b    = n0 >> 8;

    __shared__ float ctxs[4][DD + 1];
    __shared__ float wos[DD * DD];
    __shared__ float bts[DD];

    // cooperative preload (covered by the single __syncthreads below)
    if (tid < DD * DD - 128) wos[128 + tid] = wo[128 + tid];
    wos[tid] = wo[tid];
    if (tid < DD) bts[tid] = bo[tid] + theta[tid];

    // ---- K/V for head h: 8 keys per lane, loaded ONCE for 4 queries ----
    const float4* kb4 = (const float4*)(g_kT + (b * HH + h) * HD * TT);
    const float4* vb4 = (const float4*)(g_vT + (b * HH + h) * HD * TT);
    const float4 kxa = kb4[lane],       kxb = kb4[32 + lane];
    const float4 kya = kb4[64 + lane],  kyb = kb4[96 + lane];
    const float4 kza = kb4[128 + lane], kzb = kb4[160 + lane];
    const float4 vxa = vb4[lane],       vxb = vb4[32 + lane];
    const float4 vya = vb4[64 + lane],  vyb = vb4[96 + lane];
    const float4 vza = vb4[128 + lane], vzb = vb4[160 + lane];

    #pragma unroll
    for (int t = 0; t < 4; t++) {
        const float* qp = g_q + (n0 + t) * DD + h * HD;   // broadcast loads
        const float q0 = qp[0], q1 = qp[1], q2 = qp[2];   // pre-scaled

        float p[8];
        p[0] = __expf(q0*kxa.x + q1*kya.x + q2*kza.x);
        p[1] = __expf(q0*kxa.y + q1*kya.y + q2*kza.y);
        p[2] = __expf(q0*kxa.z + q1*kya.z + q2*kza.z);
        p[3] = __expf(q0*kxa.w + q1*kya.w + q2*kza.w);
        p[4] = __expf(q0*kxb.x + q1*kyb.x + q2*kzb.x);
        p[5] = __expf(q0*kxb.y + q1*kyb.y + q2*kzb.y);
        p[6] = __expf(q0*kxb.z + q1*kyb.z + q2*kzb.z);
        p[7] = __expf(q0*kxb.w + q1*kyb.w + q2*kzb.w);

        float l  = ((p[0]+p[1]) + (p[2]+p[3])) + ((p[4]+p[5]) + (p[6]+p[7]));
        float a0 = p[0]*vxa.x + p[1]*vxa.y + p[2]*vxa.z + p[3]*vxa.w
                 + p[4]*vxb.x + p[5]*vxb.y + p[6]*vxb.z + p[7]*vxb.w;
        float a1 = p[0]*vya.x + p[1]*vya.y + p[2]*vya.z + p[3]*vya.w
                 + p[4]*vyb.x + p[5]*vyb.y + p[6]*vyb.z + p[7]*vyb.w;
        float a2 = p[0]*vza.x + p[1]*vza.y + p[2]*vza.z + p[3]*vza.w
                 + p[4]*vzb.x + p[5]*vzb.y + p[6]*vzb.z + p[7]*vzb.w;

        // split reduction: 2 butterfly levels on all 4, select by lane group,
        // 3 butterfly levels on one value.
        #pragma unroll
        for (int off = 16; off >= 8; off >>= 1) {
            l  += __shfl_xor_sync(0xFFFFFFFFu, l,  off);
            a0 += __shfl_xor_sync(0xFFFFFFFFu, a0, off);
            a1 += __shfl_xor_sync(0xFFFFFFFFu, a1, off);
            a2 += __shfl_xor_sync(0xFFFFFFFFu, a2, off);
        }
        float v = (lane < 8) ? l : (lane < 16) ? a0 : (lane < 24) ? a1 : a2;
        #pragma unroll
        for (int off = 4; off >= 1; off >>= 1)
            v += __shfl_xor_sync(0xFFFFFFFFu, v, off);
        // lanes 0-7: total l ; 8-15: a0 ; 16-23: a1 ; 24-31: a2
        const float ltot = __shfl_sync(0xFFFFFFFFu, v, 0);
        if ((lane & 7) == 0 && lane != 0)
            ctxs[t][h * HD + (lane >> 3) - 1] = __fdividef(v, ltot);
    }
    __syncthreads();

    // ---- tail: warp t handles token t (lanes 0..11 active math) ----
    {
        const int t = h;                 // warp id doubles as token index
        const int w = lane;
        float c = 1.0f;
        if (w < DD) {
            float a = bts[w];
            #pragma unroll
            for (int j = 0; j < DD; j++) a = fmaf(ctxs[t][j], wos[w * DD + j], a);
            c = __cosf(a);
        }
        // inclusive product scan: d_0 = 1, d_w = c_w (1<=w<12) -> S_w = c_1..c_w
        float d = (w >= 1 && w < DD) ? c : 1.0f;
        #pragma unroll
        for (int off = 1; off <= 8; off <<= 1) {
            const float s = __shfl_up_sync(0xFFFFFFFFu, d, off);
            if (lane >= off) d *= s;
        }
        const float c0  = __shfl_sync(0xFFFFFFFFu, c, 0);
        const float s11 = __shfl_sync(0xFFFFFFFFu, d, 11);
        if (w < DD)
            out[(n0 + t) * DD + w] = (w == 0) ? s11 : c0 * d;
    }
}

extern "C" void kernel_launch(void* const* d_in, const int* in_sizes, int n_in,
                              void* d_out, int out_size)
{
    const float* x     = (const float*)d_in[0];
    const float* wq    = (const float*)d_in[1];
    const float* wk    = (const float*)d_in[2];
    const float* wv    = (const float*)d_in[3];
    const float* bq    = (const float*)d_in[4];
    const float* bk    = (const float*)d_in[5];
    const float* bv    = (const float*)d_in[6];
    const float* wo    = (const float*)d_in[7];
    const float* bo    = (const float*)d_in[8];
    const float* theta = (const float*)d_in[9];
    float* out = (float*)d_out;

    qkv_kernel<<<NTOK / 16, 192>>>(x, wq, wk, wv, bq, bk, bv);
    attn_quantum_kernel<<<NTOK / 4, 128>>>(wo, bo, theta, out);
}

// round 7
// speedup vs baseline: 1.2063x; 1.0105x over previous
#include <cuda_runtime.h>
#include <math.h>

#define BB 8
#define TT 256
#define DD 12
#define HH 4
#define HD 3
#define NTOK (BB*TT)

// scratch (no cudaMalloc allowed)
__device__ float g_q[NTOK * DD];          // [n][d] token-major, PRE-SCALED by 1/sqrt(3)
__device__ float g_kT[BB * HH * HD * TT]; // [b][h][i][t] key-major rows (float4-aligned)
__device__ float g_vT[BB * HH * HD * TT];

// ---------------------------------------------------------------------------
// K1: QKV projection, smem-staged. 16 tokens/block x 12 dims = 192 threads.
// q written pre-scaled by 1/sqrt(hd). Signals PDL dependents immediately.
// ---------------------------------------------------------------------------
__global__ __launch_bounds__(192)
void qkv_kernel(const float* __restrict__ x,
                const float* __restrict__ wq, const float* __restrict__ wk,
                const float* __restrict__ wv,
                const float* __restrict__ bq, const float* __restrict__ bk,
                const float* __restrict__ bv)
{
    // let the dependent grid launch + run its independent preamble now
    asm volatile("griddepcontrol.launch_dependents;");

    const int tid = threadIdx.x;
    const int n0  = blockIdx.x * 16;

    __shared__ float xs[16][DD + 1];
    __shared__ float wqs[DD * DD], wks[DD * DD], wvs[DD * DD];
    __shared__ float bs[3 * DD];

    if (tid < DD * DD) { wqs[tid] = wq[tid]; wks[tid] = wk[tid]; wvs[tid] = wv[tid]; }
    if (tid < DD) { bs[tid] = bq[tid]; bs[DD + tid] = bk[tid]; bs[2 * DD + tid] = bv[tid]; }
    {   // coalesced: 192 floats = 16 rows x 12
        const int r = tid / DD, c = tid - r * DD;
        xs[r][c] = x[n0 * DD + tid];
    }
    __syncthreads();

    const int t = tid / DD;
    const int d = tid - t * DD;
    const int n = n0 + t;

    float aq = bs[d], ak = bs[DD + d], av = bs[2 * DD + d];
    #pragma unroll
    for (int j = 0; j < DD; j++) {
        const float xj = xs[t][j];
        aq += xj * wqs[d * DD + j];
        ak += xj * wks[d * DD + j];
        av += xj * wvs[d * DD + j];
    }
    g_q[n * DD + d] = aq * 0.57735026919f;      // coalesced, pre-scaled

    const int b = n >> 8, tt = n & 255;
    const int h = d / HD, i = d - h * HD;
    const int base = ((b * HH + h) * HD + i) * TT + tt;
    g_kT[base] = ak;
    g_vT[base] = av;
}

// ---------------------------------------------------------------------------
// K2: fused attention + projection + analytic quantum expvals.
// Block = 4 consecutive tokens; warp h = head h for ALL 4 tokens, K/V held in
// registers across the 4 queries. No-max softmax (scores O(10), fp32-safe).
// PDL: preamble (wo/bo/theta smem preload) runs before griddepcontrol.wait,
// overlapping with the producer kernel.
//   out[k] = prod_{j=0..k} c_j (k>=1) ; out[0] = prod_{j=1..11} c_j
// ---------------------------------------------------------------------------
__global__ __launch_bounds__(128)
void attn_quantum_kernel(const float* __restrict__ wo,
                         const float* __restrict__ bo,
                         const float* __restrict__ theta,
                         float* __restrict__ out)
{
    const int tid  = threadIdx.x;
    const int h    = tid >> 5;          // warp = head
    const int lane = tid & 31;
    const int n0   = blockIdx.x * 4;    // 4 tokens, same batch (4 | 256)
    const int b    = n0 >> 8;

    __shared__ float ctxs[4][DD + 1];
    __shared__ float wos[DD * DD];
    __shared__ float bts[DD];

    // independent-input preload: overlaps with producer kernel under PDL
    if (tid < DD * DD - 128) wos[128 + tid] = wo[128 + tid];
    wos[tid] = wo[tid];
    if (tid < DD) bts[tid] = bo[tid] + theta[tid];

    // wait for producer grid's stores (g_q / g_kT / g_vT) to be visible
    asm volatile("griddepcontrol.wait;");

    // ---- K/V for head h: 8 keys per lane, loaded ONCE for 4 queries ----
    const float4* kb4 = (const float4*)(g_kT + (b * HH + h) * HD * TT);
    const float4* vb4 = (const float4*)(g_vT + (b * HH + h) * HD * TT);
    const float4 kxa = kb4[lane],       kxb = kb4[32 + lane];
    const float4 kya = kb4[64 + lane],  kyb = kb4[96 + lane];
    const float4 kza = kb4[128 + lane], kzb = kb4[160 + lane];
    const float4 vxa = vb4[lane],       vxb = vb4[32 + lane];
    const float4 vya = vb4[64 + lane],  vyb = vb4[96 + lane];
    const float4 vza = vb4[128 + lane], vzb = vb4[160 + lane];

    #pragma unroll
    for (int t = 0; t < 4; t++) {
        const float* qp = g_q + (n0 + t) * DD + h * HD;   // broadcast loads
        const float q0 = qp[0], q1 = qp[1], q2 = qp[2];   // pre-scaled

        float p[8];
        p[0] = __expf(q0*kxa.x + q1*kya.x + q2*kza.x);
        p[1] = __expf(q0*kxa.y + q1*kya.y + q2*kza.y);
        p[2] = __expf(q0*kxa.z + q1*kya.z + q2*kza.z);
        p[3] = __expf(q0*kxa.w + q1*kya.w + q2*kza.w);
        p[4] = __expf(q0*kxb.x + q1*kyb.x + q2*kzb.x);
        p[5] = __expf(q0*kxb.y + q1*kyb.y + q2*kzb.y);
        p[6] = __expf(q0*kxb.z + q1*kyb.z + q2*kzb.z);
        p[7] = __expf(q0*kxb.w + q1*kyb.w + q2*kzb.w);

        float l  = ((p[0]+p[1]) + (p[2]+p[3])) + ((p[4]+p[5]) + (p[6]+p[7]));
        float a0 = p[0]*vxa.x + p[1]*vxa.y + p[2]*vxa.z + p[3]*vxa.w
                 + p[4]*vxb.x + p[5]*vxb.y + p[6]*vxb.z + p[7]*vxb.w;
        float a1 = p[0]*vya.x + p[1]*vya.y + p[2]*vya.z + p[3]*vya.w
                 + p[4]*vyb.x + p[5]*vyb.y + p[6]*vyb.z + p[7]*vyb.w;
        float a2 = p[0]*vza.x + p[1]*vza.y + p[2]*vza.z + p[3]*vza.w
                 + p[4]*vzb.x + p[5]*vzb.y + p[6]*vzb.z + p[7]*vzb.w;

        // split reduction: 2 butterfly levels on all 4, select by lane group,
        // 3 butterfly levels on one value.
        #pragma unroll
        for (int off = 16; off >= 8; off >>= 1) {
            l  += __shfl_xor_sync(0xFFFFFFFFu, l,  off);
            a0 += __shfl_xor_sync(0xFFFFFFFFu, a0, off);
            a1 += __shfl_xor_sync(0xFFFFFFFFu, a1, off);
            a2 += __shfl_xor_sync(0xFFFFFFFFu, a2, off);
        }
        float v = (lane < 8) ? l : (lane < 16) ? a0 : (lane < 24) ? a1 : a2;
        #pragma unroll
        for (int off = 4; off >= 1; off >>= 1)
            v += __shfl_xor_sync(0xFFFFFFFFu, v, off);
        // lanes 0-7: total l ; 8-15: a0 ; 16-23: a1 ; 24-31: a2
        const float ltot = __shfl_sync(0xFFFFFFFFu, v, 0);
        if ((lane & 7) == 0 && lane != 0)
            ctxs[t][h * HD + (lane >> 3) - 1] = __fdividef(v, ltot);
    }
    __syncthreads();

    // ---- tail: warp t handles token t (lanes 0..11 active math) ----
    {
        const int t = h;                 // warp id doubles as token index
        const int w = lane;
        float c = 1.0f;
        if (w < DD) {
            float a = bts[w];
            #pragma unroll
            for (int j = 0; j < DD; j++) a = fmaf(ctxs[t][j], wos[w * DD + j], a);
            c = __cosf(a);
        }
        // inclusive product scan: d_0 = 1, d_w = c_w (1<=w<12) -> S_w = c_1..c_w
        float d = (w >= 1 && w < DD) ? c : 1.0f;
        #pragma unroll
        for (int off = 1; off <= 8; off <<= 1) {
            const float s = __shfl_up_sync(0xFFFFFFFFu, d, off);
            if (lane >= off) d *= s;
        }
        const float c0  = __shfl_sync(0xFFFFFFFFu, c, 0);
        const float s11 = __shfl_sync(0xFFFFFFFFu, d, 11);
        if (w < DD)
            out[(n0 + t) * DD + w] = (w == 0) ? s11 : c0 * d;
    }
}

extern "C" void kernel_launch(void* const* d_in, const int* in_sizes, int n_in,
                              void* d_out, int out_size)
{
    const float* x     = (const float*)d_in[0];
    const float* wq    = (const float*)d_in[1];
    const float* wk    = (const float*)d_in[2];
    const float* wv    = (const float*)d_in[3];
    const float* bq    = (const float*)d_in[4];
    const float* bk    = (const float*)d_in[5];
    const float* bv    = (const float*)d_in[6];
    const float* wo    = (const float*)d_in[7];
    const float* bo    = (const float*)d_in[8];
    const float* theta = (const float*)d_in[9];
    float* out = (float*)d_out;

    qkv_kernel<<<NTOK / 16, 192>>>(x, wq, wk, wv, bq, bk, bv);

    // PDL launch: overlap this grid's ramp + preamble with qkv_kernel
    cudaLaunchConfig_t cfg = {};
    cfg.gridDim  = dim3(NTOK / 4, 1, 1);
    cfg.blockDim = dim3(128, 1, 1);
    cfg.dynamicSmemBytes = 0;
    cfg.stream = 0;   // same (capture) stream as the <<<>>> launch above
    cudaLaunchAttribute attr[1];
    attr[0].id = cudaLaunchAttributeProgrammaticStreamSerialization;
    attr[0].val.programmaticStreamSerializationAllowed = 1;
    cfg.attrs = attr;
    cfg.numAttrs = 1;
    cudaLaunchKernelEx(&cfg, attn_quantum_kernel, wo, bo, theta, out);
}